// round 1
// baseline (speedup 1.0000x reference)
#include <cuda_runtime.h>
#include <cstdint>

#define TT   8192
#define HID  512
#define EE   256
#define ING  40
#define G0   64
#define G1   64

// ---------------- device scratch (static globals: no allocation) ------------
__device__ float    g_xg0[TT * 2048];   // 64 MB: precomputed input gates, layer 0
__device__ float    g_h1[TT * HID];     // 16 MB: layer-0 hidden history
__device__ float    g_h2[TT * HID];     // 16 MB: layer-1 hidden history
__device__ unsigned g_arr0[TT];         // per-step arrival counters, layer 0
__device__ unsigned g_arr1[TT];         // per-step arrival counters, layer 1
__device__ float    g_weff[2048 * ING]; // folded W_ih0 @ W_in
__device__ float    g_beff[2048];       // folded bias
__device__ float    g_cfin[2 * HID];    // final cell states

// ---------------- small PTX helpers -----------------------------------------
__device__ __forceinline__ unsigned ld_acq(const unsigned* p) {
    unsigned v;
    asm volatile("ld.acquire.gpu.global.u32 %0, [%1];" : "=r"(v) : "l"(p) : "memory");
    return v;
}
__device__ __forceinline__ void red_rel(unsigned* p) {
    asm volatile("red.release.gpu.global.add.u32 [%0], 1;" :: "l"(p) : "memory");
}
// packed 2xfp32 FMA (sm_100+/sm_103a only; exact fp32 semantics)
__device__ __forceinline__ unsigned long long fma2(unsigned long long a,
                                                   unsigned long long b,
                                                   unsigned long long c) {
    unsigned long long d;
    asm("fma.rn.f32x2 %0, %1, %2, %3;" : "=l"(d) : "l"(a), "l"(b), "l"(c));
    return d;
}
__device__ __forceinline__ void unpack2(unsigned long long v, float& lo, float& hi) {
    asm("mov.b64 {%0, %1}, %2;" : "=f"(lo), "=f"(hi) : "l"(v));
}
__device__ __forceinline__ float sigf(float x) { return 1.f / (1.f + __expf(-x)); }

// ---------------- reset counters (runs every launch / graph replay) ---------
__global__ void k_reset() {
    int i = blockIdx.x * blockDim.x + threadIdx.x;
    if (i < TT) { g_arr0[i] = 0u; g_arr1[i] = 0u; }
}

// ---------------- fold input projection into layer-0 input weights ----------
// Weff[j,i] = sum_e W_ih0[j,e] * W_in[e,i];  beff[j] = W_ih0[j,:]@b_in + b_ih0 + b_hh0
__global__ void k_fold(const float* __restrict__ W_ih0, const float* __restrict__ W_in,
                       const float* __restrict__ b_in,  const float* __restrict__ b_ih0,
                       const float* __restrict__ b_hh0) {
    __shared__ float srow[EE];
    int j = blockIdx.x;
    for (int e = threadIdx.x; e < EE; e += 64) srow[e] = W_ih0[(size_t)j * EE + e];
    __syncthreads();
    if (threadIdx.x < ING) {
        int i = threadIdx.x;
        float s = 0.f;
        #pragma unroll 8
        for (int e = 0; e < EE; ++e) s += srow[e] * W_in[e * ING + i];
        g_weff[(size_t)j * ING + i] = s;
    } else if (threadIdx.x == ING) {
        float s = 0.f;
        #pragma unroll 8
        for (int e = 0; e < EE; ++e) s += srow[e] * b_in[e];
        g_beff[j] = s + b_ih0[j] + b_hh0[j];
    }
}

// ---------------- precompute xg0[t][j] = in_states[t] @ Weff[j] + beff[j] ---
__global__ void k_xg0(const float* __restrict__ in_states) {
    __shared__ float s_in[16 * ING];
    const int t0 = blockIdx.y * 16;
    const int j  = blockIdx.x * 256 + threadIdx.x;
    for (int idx = threadIdx.x; idx < 16 * ING; idx += 256)
        s_in[idx] = in_states[(size_t)t0 * ING + idx];
    __syncthreads();

    float wreg[ING];
    const float4* wp = (const float4*)(g_weff + (size_t)j * ING);
    #pragma unroll
    for (int u = 0; u < ING / 4; ++u) ((float4*)wreg)[u] = wp[u];

    float acc[16];
    float b = g_beff[j];
    #pragma unroll
    for (int tt = 0; tt < 16; ++tt) acc[tt] = b;
    #pragma unroll
    for (int i = 0; i < ING; ++i) {
        float wv = wreg[i];
        #pragma unroll
        for (int tt = 0; tt < 16; ++tt) acc[tt] += wv * s_in[tt * ING + i];
    }
    #pragma unroll
    for (int tt = 0; tt < 16; ++tt)
        g_xg0[(size_t)(t0 + tt) * 2048 + j] = acc[tt];
}

// ---------------- persistent recurrent kernel: both LSTM layers -------------
// blocks 0..63   : layer 0  (gates = W_hh0 @ h1[t-1] + xg0[t])
// blocks 64..127 : layer 1  (gates = W_ih1 @ h1[t] + W_hh1 @ h2[t-1] + bias)
// Each CTA owns 8 cell indices m (32 gate rows). Thread layout:
//   warp w (0..15) = k-chunk [w*32, w*32+32), lane r (0..31) = local gate row.
// Weights live in registers (packed f32x2). h staged to SMEM, broadcast LDS.
__global__ void __launch_bounds__(512, 1) k_rec(
    const float* __restrict__ W_hh0, const float* __restrict__ W_ih1,
    const float* __restrict__ W_hh1, const float* __restrict__ b_ih1,
    const float* __restrict__ b_hh1) {
    __shared__ __align__(16) float sh1[HID];
    __shared__ __align__(16) float sh2[HID];
    __shared__ float part[512];

    const int  tid  = threadIdx.x;
    const int  w    = tid >> 5;   // k-chunk (warp id)
    const int  r    = tid & 31;   // local gate row
    const bool isL0 = (blockIdx.x < G0);
    const int  cl   = isL0 ? blockIdx.x : (blockIdx.x - G0);
    const int  m0   = cl * 8;
    const int  q    = r >> 3, ml = r & 7;
    const int  grow = q * 512 + m0 + ml;   // global gate row (i,f,g,o blocks)

    // load weights to registers as packed fp32 pairs
    unsigned long long wa[16], wb[16];
    {
        const unsigned long long* pa = (const unsigned long long*)(
            (isL0 ? W_hh0 : W_ih1) + (size_t)grow * HID + w * 32);
        #pragma unroll
        for (int u = 0; u < 16; ++u) wa[u] = pa[u];
        if (isL0) {
            #pragma unroll
            for (int u = 0; u < 16; ++u) wb[u] = 0ull;
        } else {
            const unsigned long long* pb = (const unsigned long long*)(
                W_hh1 + (size_t)grow * HID + w * 32);
            #pragma unroll
            for (int u = 0; u < 16; ++u) wb[u] = pb[u];
        }
    }
    const float bias_c = isL0 ? 0.f : (b_ih1[grow] + b_hh1[grow]);

    if (isL0 && tid < 128) *(float4*)&sh2[tid * 4] = make_float4(0, 0, 0, 0);

    float creg = 0.f;

    for (int t = 0; t < TT; ++t) {
        // ---- wait for producers (one thread spins on L2 counters) ----
        if (tid == 0) {
            if (isL0) {
                if (t > 0) while (ld_acq(&g_arr0[t - 1]) < G0) {}
            } else {
                while (ld_acq(&g_arr0[t]) < G0) {}
                if (t > 0) while (ld_acq(&g_arr1[t - 1]) < G1) {}
            }
        }
        __syncthreads();

        // ---- stage h vectors into SMEM ----
        if (isL0) {
            if (tid < 128) {
                float4 v = (t > 0) ? *(const float4*)&g_h1[(size_t)(t - 1) * HID + tid * 4]
                                   : make_float4(0, 0, 0, 0);
                *(float4*)&sh1[tid * 4] = v;
            }
        } else {
            if (tid < 128) {
                *(float4*)&sh1[tid * 4] = *(const float4*)&g_h1[(size_t)t * HID + tid * 4];
            } else if (tid < 256) {
                int i = tid - 128;
                float4 v = (t > 0) ? *(const float4*)&g_h2[(size_t)(t - 1) * HID + i * 4]
                                   : make_float4(0, 0, 0, 0);
                *(float4*)&sh2[i * 4] = v;
            }
        }
        float extra = bias_c;
        if (w == 0 && isL0) extra = __ldg(&g_xg0[(size_t)t * 2048 + grow]);  // hidden by FMA
        __syncthreads();

        // ---- GEMV slice: packed f32x2 FMAs, broadcast LDS for h ----
        unsigned long long acc2 = 0ull;
        const unsigned long long* h1p = (const unsigned long long*)(sh1 + w * 32);
        const unsigned long long* h2p = (const unsigned long long*)(sh2 + w * 32);
        #pragma unroll
        for (int u = 0; u < 16; ++u) acc2 = fma2(wa[u], h1p[u], acc2);
        #pragma unroll
        for (int u = 0; u < 16; ++u) acc2 = fma2(wb[u], h2p[u], acc2);
        float alo, ahi; unpack2(acc2, alo, ahi);
        part[w * 32 + r] = alo + ahi;
        __syncthreads();

        // ---- warp 0: cross-warp reduce, gates, cell update, publish ----
        if (w == 0) {
            float s = extra;
            #pragma unroll
            for (int u = 0; u < 16; ++u) s += part[u * 32 + r];  // bank-conflict free
            float pi = __shfl_sync(0xffffffffu, s, ml);
            float pf = __shfl_sync(0xffffffffu, s, 8 + ml);
            float pg = __shfl_sync(0xffffffffu, s, 16 + ml);
            float po = __shfl_sync(0xffffffffu, s, 24 + ml);
            if (r < 8) {
                float ig = sigf(pi), fg = sigf(pf), gg = tanhf(pg), og = sigf(po);
                creg = fg * creg + ig * gg;
                float h = og * tanhf(creg);
                float* dst = isL0 ? g_h1 : g_h2;
                dst[(size_t)t * HID + m0 + r] = h;
            }
            __syncwarp();
            if (r == 0) red_rel(isL0 ? &g_arr0[t] : &g_arr1[t]);
        }
    }

    if (w == 0 && r < 8) g_cfin[(isL0 ? 0 : HID) + m0 + r] = creg;
}

// ---------------- output projection + final states --------------------------
__global__ void k_out(const float* __restrict__ W_out, const float* __restrict__ b_out,
                      float* __restrict__ out, int out_size) {
    int wid = threadIdx.x >> 5, lane = threadIdx.x & 31;
    int t = blockIdx.x * 8 + wid;
    float acc = 0.f;
    #pragma unroll
    for (int j = 0; j < 16; ++j) {
        int k = j * 32 + lane;
        acc += g_h2[(size_t)t * HID + k] * W_out[k];
    }
    #pragma unroll
    for (int o = 16; o; o >>= 1) acc += __shfl_down_sync(0xffffffffu, acc, o);
    if (lane == 0 && t < out_size) out[t] = acc + b_out[0];

    // h_final = stack(h1_T, h2_T); c_final = stack(c1_T, c2_T) — guarded by out_size
    if (blockIdx.x == 0 && out_size >= TT + 2048) {
        for (int i = threadIdx.x; i < 512; i += 256) {
            out[TT + i]        = g_h1[(size_t)(TT - 1) * HID + i];
            out[TT + 512 + i]  = g_h2[(size_t)(TT - 1) * HID + i];
            out[TT + 1024 + i] = g_cfin[i];
            out[TT + 1536 + i] = g_cfin[512 + i];
        }
    }
}

// ---------------- launch -----------------------------------------------------
extern "C" void kernel_launch(void* const* d_in, const int* in_sizes, int n_in,
                              void* d_out, int out_size) {
    const float* in_states = (const float*)d_in[0];
    const float* W_in  = (const float*)d_in[1];
    const float* b_in  = (const float*)d_in[2];
    const float* W_ih0 = (const float*)d_in[3];
    const float* W_hh0 = (const float*)d_in[4];
    const float* b_ih0 = (const float*)d_in[5];
    const float* b_hh0 = (const float*)d_in[6];
    const float* W_ih1 = (const float*)d_in[7];
    const float* W_hh1 = (const float*)d_in[8];
    const float* b_ih1 = (const float*)d_in[9];
    const float* b_hh1 = (const float*)d_in[10];
    const float* W_out = (const float*)d_in[11];
    const float* b_out = (const float*)d_in[12];

    k_reset<<<(TT + 1023) / 1024, 1024>>>();
    k_fold<<<2048, 64>>>(W_ih0, W_in, b_in, b_ih0, b_hh0);
    k_xg0<<<dim3(2048 / 256, TT / 16), 256>>>(in_states);
    k_rec<<<G0 + G1, 512>>>(W_hh0, W_ih1, W_hh1, b_ih1, b_hh1);
    k_out<<<TT / 8, 256>>>(W_out, b_out, (float*)d_out, out_size);
}

// round 2
// speedup vs baseline: 1.0609x; 1.0609x over previous
#include <cuda_runtime.h>
#include <cstdint>

#define TT   8192
#define HID  512
#define EE   256
#define ING  40
#define G0   64
#define G1   64

typedef unsigned long long ULL;

// ---------------- device scratch (static globals: no allocation) ------------
__device__ float    g_xg0[TT * 2048];   // 64 MB: precomputed input gates, layer 0
__device__ float    g_h1[TT * HID];     // 16 MB: layer-0 hidden history
__device__ float    g_h2[TT * HID];     // 16 MB: layer-1 hidden history
__device__ unsigned g_arr0[TT];         // per-step arrival counters, layer 0
__device__ unsigned g_arr1[TT];         // per-step arrival counters, layer 1
__device__ float    g_weff[2048 * ING]; // folded W_ih0 @ W_in
__device__ float    g_beff[2048];       // folded bias
__device__ float    g_cfin[2 * HID];    // final cell states

// ---------------- small PTX helpers -----------------------------------------
__device__ __forceinline__ unsigned ld_acq(const unsigned* p) {
    unsigned v;
    asm volatile("ld.acquire.gpu.global.u32 %0, [%1];" : "=r"(v) : "l"(p) : "memory");
    return v;
}
__device__ __forceinline__ void red_rel(unsigned* p) {
    asm volatile("red.release.gpu.global.add.u32 [%0], 1;" :: "l"(p) : "memory");
}
// packed 2xfp32 FMA / ADD (sm_103a; exact fp32 semantics)
__device__ __forceinline__ ULL fma2(ULL a, ULL b, ULL c) {
    ULL d;
    asm("fma.rn.f32x2 %0, %1, %2, %3;" : "=l"(d) : "l"(a), "l"(b), "l"(c));
    return d;
}
__device__ __forceinline__ ULL add2(ULL a, ULL b) {
    ULL d;
    asm("add.rn.f32x2 %0, %1, %2;" : "=l"(d) : "l"(a), "l"(b));
    return d;
}
__device__ __forceinline__ void unpack2(ULL v, float& lo, float& hi) {
    asm("mov.b64 {%0, %1}, %2;" : "=f"(lo), "=f"(hi) : "l"(v));
}
// MUFU-based fast activations (abs err ~1e-6)
__device__ __forceinline__ float ex2f(float x) {
    float y; asm("ex2.approx.f32 %0, %1;" : "=f"(y) : "f"(x)); return y;
}
__device__ __forceinline__ float rcpf(float x) {
    float y; asm("rcp.approx.f32 %0, %1;" : "=f"(y) : "f"(x)); return y;
}
__device__ __forceinline__ float sigf(float x) {
    return rcpf(1.f + ex2f(-1.4426950408889634f * x));   // 1/(1+e^-x)
}
__device__ __forceinline__ float tanhf_fast(float x) {
    return fmaf(-2.f, rcpf(1.f + ex2f(2.8853900817779268f * x)), 1.f); // 1-2/(e^2x+1)
}

// ---------------- reset counters (runs every launch / graph replay) ---------
__global__ void k_reset() {
    int i = blockIdx.x * blockDim.x + threadIdx.x;
    if (i < TT) { g_arr0[i] = 0u; g_arr1[i] = 0u; }
}

// ---------------- fold input projection into layer-0 input weights ----------
__global__ void k_fold(const float* __restrict__ W_ih0, const float* __restrict__ W_in,
                       const float* __restrict__ b_in,  const float* __restrict__ b_ih0,
                       const float* __restrict__ b_hh0) {
    __shared__ float srow[EE];
    int j = blockIdx.x;
    for (int e = threadIdx.x; e < EE; e += 64) srow[e] = W_ih0[(size_t)j * EE + e];
    __syncthreads();
    if (threadIdx.x < ING) {
        int i = threadIdx.x;
        float s = 0.f;
        #pragma unroll 8
        for (int e = 0; e < EE; ++e) s += srow[e] * W_in[e * ING + i];
        g_weff[(size_t)j * ING + i] = s;
    } else if (threadIdx.x == ING) {
        float s = 0.f;
        #pragma unroll 8
        for (int e = 0; e < EE; ++e) s += srow[e] * b_in[e];
        g_beff[j] = s + b_ih0[j] + b_hh0[j];
    }
}

// ---------------- precompute xg0[t][j] = in_states[t] @ Weff[j] + beff[j] ---
__global__ void k_xg0(const float* __restrict__ in_states) {
    __shared__ float s_in[16 * ING];
    const int t0 = blockIdx.y * 16;
    const int j  = blockIdx.x * 256 + threadIdx.x;
    for (int idx = threadIdx.x; idx < 16 * ING; idx += 256)
        s_in[idx] = in_states[(size_t)t0 * ING + idx];
    __syncthreads();

    float wreg[ING];
    const float4* wp = (const float4*)(g_weff + (size_t)j * ING);
    #pragma unroll
    for (int u = 0; u < ING / 4; ++u) ((float4*)wreg)[u] = wp[u];

    float acc[16];
    float b = g_beff[j];
    #pragma unroll
    for (int tt = 0; tt < 16; ++tt) acc[tt] = b;
    #pragma unroll
    for (int i = 0; i < ING; ++i) {
        float wv = wreg[i];
        #pragma unroll
        for (int tt = 0; tt < 16; ++tt) acc[tt] += wv * s_in[tt * ING + i];
    }
    #pragma unroll
    for (int tt = 0; tt < 16; ++tt)
        g_xg0[(size_t)(t0 + tt) * 2048 + j] = acc[tt];
}

// ---------------- persistent recurrent kernel: both LSTM layers -------------
// blocks 0..63   : layer 0  (gates = W_hh0 @ h1[t-1] + xg0[t])
// blocks 64..127 : layer 1  (gates = W_ih1 @ h1[t] + W_hh1 @ h2[t-1] + bias)
// Warp w = k-chunk [32w,32w+32), lane r = local gate row. Each warp stages its
// own 32-float h slice (poll -> ldcg -> sts -> syncwarp). One syncthreads/step
// (part[] double-buffered). Layer 1 computes the W_ih1 half before its
// recurrent wait (layer 0 runs ahead). xg0 is prefetched one step ahead.
__global__ void __launch_bounds__(512, 1) k_rec(
    const float* __restrict__ W_hh0, const float* __restrict__ W_ih1,
    const float* __restrict__ W_hh1, const float* __restrict__ b_ih1,
    const float* __restrict__ b_hh1) {
    __shared__ __align__(16) float sh1[HID];       // L1: h1[t] slices
    __shared__ __align__(16) float sh2[HID];       // recurrent h(t-1) slices
    __shared__ __align__(16) float part[2][512];
    __shared__ int s_fA, s_fB;

    const int  tid  = threadIdx.x;
    const int  w    = tid >> 5;
    const int  r    = tid & 31;
    const bool isL0 = (blockIdx.x < G0);
    const int  cl   = isL0 ? blockIdx.x : (blockIdx.x - G0);
    const int  m0   = cl * 8;
    const int  q    = r >> 3, ml = r & 7;
    const int  grow = q * 512 + m0 + ml;           // global gate row

    // recurrent weights in registers (packed f32x2)
    ULL wa[16];
    {
        const ULL* pa = (const ULL*)((isL0 ? W_hh0 : W_hh1) + (size_t)grow * HID + w * 32);
        #pragma unroll
        for (int u = 0; u < 16; ++u) wa[u] = pa[u];
    }
    ULL wb[16];                                    // L1 only: W_ih1
    if (!isL0) {
        const ULL* pb = (const ULL*)(W_ih1 + (size_t)grow * HID + w * 32);
        #pragma unroll
        for (int u = 0; u < 16; ++u) wb[u] = pb[u];
    }
    const float bias_c = isL0 ? 0.f : (b_ih1[grow] + b_hh1[grow]);

    if (tid == 0) { s_fA = 0; s_fB = 0; }
    __syncthreads();

    unsigned* arr_self       = isL0 ? g_arr0 : g_arr1;
    const float* hprev_base  = isL0 ? g_h1   : g_h2;
    float*       hout        = isL0 ? g_h1   : g_h2;

    float creg = 0.f;
    float xg_next = 0.f;
    if (isL0 && w == 0) xg_next = __ldcg(&g_xg0[grow]);     // t = 0

    for (int t = 0; t < TT; ++t) {
        // prefetch xg0 for next step (DRAM latency hidden behind spins/compute)
        float xg_cur = xg_next;
        if (isL0 && w == 0 && t + 1 < TT)
            xg_next = __ldcg(&g_xg0[(size_t)(t + 1) * 2048 + grow]);

        ULL a0 = 0, a1 = 0, a2 = 0, a3 = 0;

        // ---- phase A (L1 only): h1[t] is ready early; do W_ih1 half now ----
        if (!isL0) {
            if (w == 0) {
                if (r == 0) { while (ld_acq(&g_arr0[t]) < (unsigned)G0) {} }
                __syncwarp();
                if (r == 0) *(volatile int*)&s_fA = t + 1;
            } else {
                while (*(volatile int*)&s_fA < t + 1) {}
            }
            asm volatile("" ::: "memory");
            if (r < 8) {
                float4 v = __ldcg((const float4*)&g_h1[(size_t)t * HID + w * 32 + r * 4]);
                *(float4*)&sh1[w * 32 + r * 4] = v;
            }
            __syncwarp();
            const ULL* hp = (const ULL*)(sh1 + w * 32);
            #pragma unroll
            for (int u = 0; u < 4; ++u) {
                a0 = fma2(wb[4 * u + 0], hp[4 * u + 0], a0);
                a1 = fma2(wb[4 * u + 1], hp[4 * u + 1], a1);
                a2 = fma2(wb[4 * u + 2], hp[4 * u + 2], a2);
                a3 = fma2(wb[4 * u + 3], hp[4 * u + 3], a3);
            }
        }

        // ---- phase B: recurrent h(t-1) ----
        if (t > 0) {
            if (w == 0) {
                if (r == 0) { while (ld_acq(&arr_self[t - 1]) < (unsigned)G0) {} }
                __syncwarp();
                if (r == 0) *(volatile int*)&s_fB = t + 1;
            } else {
                while (*(volatile int*)&s_fB < t + 1) {}
            }
            asm volatile("" ::: "memory");
            if (r < 8) {
                float4 v = __ldcg((const float4*)&hprev_base[(size_t)(t - 1) * HID + w * 32 + r * 4]);
                *(float4*)&sh2[w * 32 + r * 4] = v;
            }
        } else {
            if (r < 8) *(float4*)&sh2[w * 32 + r * 4] = make_float4(0, 0, 0, 0);
        }
        __syncwarp();
        {
            const ULL* hq = (const ULL*)(sh2 + w * 32);
            #pragma unroll
            for (int u = 0; u < 4; ++u) {
                a0 = fma2(wa[4 * u + 0], hq[4 * u + 0], a0);
                a1 = fma2(wa[4 * u + 1], hq[4 * u + 1], a1);
                a2 = fma2(wa[4 * u + 2], hq[4 * u + 2], a2);
                a3 = fma2(wa[4 * u + 3], hq[4 * u + 3], a3);
            }
        }
        {
            ULL s = add2(add2(a0, a1), add2(a2, a3));
            float alo, ahi; unpack2(s, alo, ahi);
            part[t & 1][w * 32 + r] = alo + ahi;
        }
        __syncthreads();   // the only CTA-wide barrier per step

        // ---- warp 0: reduce, gates, cell update, publish ----
        if (w == 0) {
            const float* pbuf = part[t & 1];
            float v[16];
            #pragma unroll
            for (int u = 0; u < 16; ++u) v[u] = pbuf[u * 32 + r];
            float s0 = (v[0] + v[1]) + (v[2] + v[3]);
            float s1 = (v[4] + v[5]) + (v[6] + v[7]);
            float s2 = (v[8] + v[9]) + (v[10] + v[11]);
            float s3 = (v[12] + v[13]) + (v[14] + v[15]);
            float s  = ((s0 + s1) + (s2 + s3)) + (isL0 ? xg_cur : bias_c);

            float pi = __shfl_sync(0xffffffffu, s, ml);
            float pf = __shfl_sync(0xffffffffu, s, 8 + ml);
            float pg = __shfl_sync(0xffffffffu, s, 16 + ml);
            float po = __shfl_sync(0xffffffffu, s, 24 + ml);
            if (r < 8) {
                float ig = sigf(pi), fg = sigf(pf);
                float gg = tanhf_fast(pg), og = sigf(po);
                creg = fg * creg + ig * gg;
                float h = og * tanhf_fast(creg);
                hout[(size_t)t * HID + m0 + r] = h;
            }
            __syncwarp();
            if (r == 0) red_rel(&arr_self[t]);
        }
    }

    if (w == 0 && r < 8) g_cfin[(isL0 ? 0 : HID) + m0 + r] = creg;
}

// ---------------- output projection + final states --------------------------
__global__ void k_out(const float* __restrict__ W_out, const float* __restrict__ b_out,
                      float* __restrict__ out, int out_size) {
    int wid = threadIdx.x >> 5, lane = threadIdx.x & 31;
    int t = blockIdx.x * 8 + wid;
    float acc = 0.f;
    #pragma unroll
    for (int j = 0; j < 16; ++j) {
        int k = j * 32 + lane;
        acc += g_h2[(size_t)t * HID + k] * W_out[k];
    }
    #pragma unroll
    for (int o = 16; o; o >>= 1) acc += __shfl_down_sync(0xffffffffu, acc, o);
    if (lane == 0 && t < out_size) out[t] = acc + b_out[0];

    if (blockIdx.x == 0 && out_size >= TT + 2048) {
        for (int i = threadIdx.x; i < 512; i += 256) {
            out[TT + i]        = g_h1[(size_t)(TT - 1) * HID + i];
            out[TT + 512 + i]  = g_h2[(size_t)(TT - 1) * HID + i];
            out[TT + 1024 + i] = g_cfin[i];
            out[TT + 1536 + i] = g_cfin[512 + i];
        }
    }
}

// ---------------- launch -----------------------------------------------------
extern "C" void kernel_launch(void* const* d_in, const int* in_sizes, int n_in,
                              void* d_out, int out_size) {
    const float* in_states = (const float*)d_in[0];
    const float* W_in  = (const float*)d_in[1];
    const float* b_in  = (const float*)d_in[2];
    const float* W_ih0 = (const float*)d_in[3];
    const float* W_hh0 = (const float*)d_in[4];
    const float* b_ih0 = (const float*)d_in[5];
    const float* b_hh0 = (const float*)d_in[6];
    const float* W_ih1 = (const float*)d_in[7];
    const float* W_hh1 = (const float*)d_in[8];
    const float* b_ih1 = (const float*)d_in[9];
    const float* b_hh1 = (const float*)d_in[10];
    const float* W_out = (const float*)d_in[11];
    const float* b_out = (const float*)d_in[12];

    k_reset<<<(TT + 1023) / 1024, 1024>>>();
    k_fold<<<2048, 64>>>(W_ih0, W_in, b_in, b_ih0, b_hh0);
    k_xg0<<<dim3(2048 / 256, TT / 16), 256>>>(in_states);
    k_rec<<<G0 + G1, 512>>>(W_hh0, W_ih1, W_hh1, b_ih1, b_hh1);
    k_out<<<TT / 8, 256>>>(W_out, b_out, (float*)d_out, out_size);
}

// round 3
// speedup vs baseline: 2.0455x; 1.9281x over previous
#include <cuda_runtime.h>
#include <cstdint>

#define TT   8192
#define HID  512
#define EE   256
#define ING  40
#define G0   64
#define G1   64

typedef unsigned long long ULL;

// ---------------- device scratch (static globals: no allocation) ------------
__device__ float g_xg0[TT * 2048];    // 64 MB: precomputed input gates, layer 0
__device__ ULL   g_th1[TT * HID];     // 32 MB: tagged h1 history {tag<<32 | f32}
__device__ ULL   g_th2[TT * HID];     // 32 MB: tagged h2 history
__device__ float g_weff[2048 * ING];  // folded W_ih0 @ W_in
__device__ float g_beff[2048];        // folded bias
__device__ float g_cfin[2 * HID];     // final cell states

// ---------------- PTX helpers ------------------------------------------------
__device__ __forceinline__ ULL ld_rlx(const ULL* p) {
    ULL v;
    asm volatile("ld.relaxed.gpu.global.b64 %0, [%1];" : "=l"(v) : "l"(p) : "memory");
    return v;
}
__device__ __forceinline__ void st_rlx(ULL* p, ULL v) {
    asm volatile("st.relaxed.gpu.global.b64 [%0], %1;" :: "l"(p), "l"(v) : "memory");
}
__device__ __forceinline__ ULL fma2(ULL a, ULL b, ULL c) {
    ULL d;
    asm("fma.rn.f32x2 %0, %1, %2, %3;" : "=l"(d) : "l"(a), "l"(b), "l"(c));
    return d;
}
__device__ __forceinline__ ULL add2(ULL a, ULL b) {
    ULL d;
    asm("add.rn.f32x2 %0, %1, %2;" : "=l"(d) : "l"(a), "l"(b));
    return d;
}
__device__ __forceinline__ void unpack2(ULL v, float& lo, float& hi) {
    asm("mov.b64 {%0, %1}, %2;" : "=f"(lo), "=f"(hi) : "l"(v));
}
__device__ __forceinline__ float ex2f(float x) {
    float y; asm("ex2.approx.f32 %0, %1;" : "=f"(y) : "f"(x)); return y;
}
__device__ __forceinline__ float rcpf(float x) {
    float y; asm("rcp.approx.f32 %0, %1;" : "=f"(y) : "f"(x)); return y;
}
__device__ __forceinline__ float sigf(float x) {
    return rcpf(1.f + ex2f(-1.4426950408889634f * x));
}
__device__ __forceinline__ float tanhf_fast(float x) {
    return fmaf(-2.f, rcpf(1.f + ex2f(2.8853900817779268f * x)), 1.f);
}

// ---------------- clear tag arrays (must run every launch / replay) ---------
__global__ void k_clear() {
    size_t i = (size_t)blockIdx.x * blockDim.x + threadIdx.x;   // 2,097,152 threads
    ulonglong2 z = make_ulonglong2(0ull, 0ull);
    ((ulonglong2*)g_th1)[i] = z;
    ((ulonglong2*)g_th2)[i] = z;
}

// ---------------- fold input projection into layer-0 input weights ----------
__global__ void k_fold(const float* __restrict__ W_ih0, const float* __restrict__ W_in,
                       const float* __restrict__ b_in,  const float* __restrict__ b_ih0,
                       const float* __restrict__ b_hh0) {
    __shared__ float srow[EE];
    int j = blockIdx.x;
    for (int e = threadIdx.x; e < EE; e += 64) srow[e] = W_ih0[(size_t)j * EE + e];
    __syncthreads();
    if (threadIdx.x < ING) {
        int i = threadIdx.x;
        float s = 0.f;
        #pragma unroll 8
        for (int e = 0; e < EE; ++e) s += srow[e] * W_in[e * ING + i];
        g_weff[(size_t)j * ING + i] = s;
    } else if (threadIdx.x == ING) {
        float s = 0.f;
        #pragma unroll 8
        for (int e = 0; e < EE; ++e) s += srow[e] * b_in[e];
        g_beff[j] = s + b_ih0[j] + b_hh0[j];
    }
}

// ---------------- precompute xg0[t][j] = in_states[t] @ Weff[j] + beff[j] ---
__global__ void k_xg0(const float* __restrict__ in_states) {
    __shared__ float s_in[16 * ING];
    const int t0 = blockIdx.y * 16;
    const int j  = blockIdx.x * 256 + threadIdx.x;
    for (int idx = threadIdx.x; idx < 16 * ING; idx += 256)
        s_in[idx] = in_states[(size_t)t0 * ING + idx];
    __syncthreads();

    float wreg[ING];
    const float4* wp = (const float4*)(g_weff + (size_t)j * ING);
    #pragma unroll
    for (int u = 0; u < ING / 4; ++u) ((float4*)wreg)[u] = wp[u];

    float acc[16];
    float b = g_beff[j];
    #pragma unroll
    for (int tt = 0; tt < 16; ++tt) acc[tt] = b;
    #pragma unroll
    for (int i = 0; i < ING; ++i) {
        float wv = wreg[i];
        #pragma unroll
        for (int tt = 0; tt < 16; ++tt) acc[tt] += wv * s_in[tt * ING + i];
    }
    #pragma unroll
    for (int tt = 0; tt < 16; ++tt)
        g_xg0[(size_t)(t0 + tt) * 2048 + j] = acc[tt];
}

// ---------------- persistent recurrent kernel: both LSTM layers -------------
// blocks 0..63: layer 0;  blocks 64..127: layer 1.
// Readiness = tag embedded in the 64-bit h word itself (single L2 hop).
// Warp w owns k-chunk [32w,32w+32); lane r polls its own tagged word.
// Layer 1 polls both dependencies concurrently. One CTA barrier per step.
__global__ void __launch_bounds__(512, 1) k_rec(
    const float* __restrict__ W_hh0, const float* __restrict__ W_ih1,
    const float* __restrict__ W_hh1, const float* __restrict__ b_ih1,
    const float* __restrict__ b_hh1) {
    __shared__ __align__(16) float sh1[HID];        // L1: h1[t] slices
    __shared__ __align__(16) float sh2[HID];        // recurrent h(t-1) slices
    __shared__ __align__(16) float part[2][512];

    const int  tid  = threadIdx.x;
    const int  w    = tid >> 5;
    const int  r    = tid & 31;
    const bool isL0 = (blockIdx.x < G0);
    const int  cl   = isL0 ? blockIdx.x : (blockIdx.x - G0);
    const int  m0   = cl * 8;
    const int  q    = r >> 3, ml = r & 7;
    const int  grow = q * 512 + m0 + ml;            // global gate row

    // recurrent (and L1 input) weights in registers, packed f32x2
    ULL wa[16];
    {
        const ULL* pa = (const ULL*)((isL0 ? W_hh0 : W_hh1) + (size_t)grow * HID + w * 32);
        #pragma unroll
        for (int u = 0; u < 16; ++u) wa[u] = pa[u];
    }
    ULL wb[16];
    if (!isL0) {
        const ULL* pb = (const ULL*)(W_ih1 + (size_t)grow * HID + w * 32);
        #pragma unroll
        for (int u = 0; u < 16; ++u) wb[u] = pb[u];
    }
    const float bias_c = isL0 ? 0.f : (b_ih1[grow] + b_hh1[grow]);

    ULL* trec = isL0 ? g_th1 : g_th2;    // own recurrent stream (read t-1, write t)

    float creg = 0.f;
    float xg_next = 0.f, xg_next2 = 0.f;
    if (isL0 && w == 0) {
        xg_next  = __ldcg(&g_xg0[grow]);                      // t = 0
        xg_next2 = __ldcg(&g_xg0[2048 + grow]);               // t = 1
    }

    for (int t = 0; t < TT; ++t) {
        float xg_cur = xg_next;
        xg_next = xg_next2;
        if (isL0 && w == 0 && t + 2 < TT)
            xg_next2 = __ldcg(&g_xg0[(size_t)(t + 2) * 2048 + grow]);

        // ---- concurrent polls on tagged words (one L2 hop each) ----
        const ULL* pA = g_th1 + (size_t)t * HID + w * 32 + r;        // L1: h1[t]
        const ULL* pB = trec + (size_t)(t - 1) * HID + w * 32 + r;   // h(t-1)
        const unsigned wantA = (unsigned)(t + 1);
        const unsigned wantB = (unsigned)t;
        ULL va = 0, vb = 0;
        bool needA = !isL0;
        bool needB = (t > 0);
        while (needA || needB) {
            if (needA) { va = ld_rlx(pA); needA = ((unsigned)(va >> 32) != wantA); }
            if (needB) { vb = ld_rlx(pB); needB = ((unsigned)(vb >> 32) != wantB); }
        }

        // ---- stage slices (each warp touches only its own 32-float slice) ----
        if (!isL0) sh1[w * 32 + r] = __uint_as_float((unsigned)va);
        sh2[w * 32 + r] = (t > 0) ? __uint_as_float((unsigned)vb) : 0.f;
        __syncwarp();

        // ---- GEMV slice: packed f32x2 FMAs, broadcast LDS ----
        ULL a0 = 0, a1 = 0, a2 = 0, a3 = 0;
        {
            const ULL* hq = (const ULL*)(sh2 + w * 32);
            #pragma unroll
            for (int u = 0; u < 4; ++u) {
                a0 = fma2(wa[4 * u + 0], hq[4 * u + 0], a0);
                a1 = fma2(wa[4 * u + 1], hq[4 * u + 1], a1);
                a2 = fma2(wa[4 * u + 2], hq[4 * u + 2], a2);
                a3 = fma2(wa[4 * u + 3], hq[4 * u + 3], a3);
            }
        }
        if (!isL0) {
            const ULL* hp = (const ULL*)(sh1 + w * 32);
            #pragma unroll
            for (int u = 0; u < 4; ++u) {
                a0 = fma2(wb[4 * u + 0], hp[4 * u + 0], a0);
                a1 = fma2(wb[4 * u + 1], hp[4 * u + 1], a1);
                a2 = fma2(wb[4 * u + 2], hp[4 * u + 2], a2);
                a3 = fma2(wb[4 * u + 3], hp[4 * u + 3], a3);
            }
        }
        {
            ULL s = add2(add2(a0, a1), add2(a2, a3));
            float alo, ahi; unpack2(s, alo, ahi);
            part[t & 1][w * 32 + r] = alo + ahi;
        }
        __syncthreads();   // the only CTA-wide barrier per step

        // ---- warp 0: reduce, per-lane activation, shuffle, cell update ----
        if (w == 0) {
            const float* pbuf = part[t & 1];
            float v[16];
            #pragma unroll
            for (int u = 0; u < 16; ++u) v[u] = pbuf[u * 32 + r];
            float s0 = (v[0] + v[1]) + (v[2] + v[3]);
            float s1 = (v[4] + v[5]) + (v[6] + v[7]);
            float s2 = (v[8] + v[9]) + (v[10] + v[11]);
            float s3 = (v[12] + v[13]) + (v[14] + v[15]);
            float s  = ((s0 + s1) + (s2 + s3)) + (isL0 ? xg_cur : bias_c);

            // activation in ALL lanes first (q==2 -> tanh gate, else sigmoid)
            float act = (q == 2) ? tanhf_fast(s) : sigf(s);
            float pi = __shfl_sync(0xffffffffu, act, ml);
            float pf = __shfl_sync(0xffffffffu, act, 8 + ml);
            float pg = __shfl_sync(0xffffffffu, act, 16 + ml);
            float po = __shfl_sync(0xffffffffu, act, 24 + ml);
            if (r < 8) {
                creg = pf * creg + pi * pg;
                float h = po * tanhf_fast(creg);
                ULL word = ((ULL)(unsigned)(t + 1) << 32) | (ULL)__float_as_uint(h);
                st_rlx(&trec[(size_t)t * HID + m0 + r], word);
            }
        }
    }

    if (w == 0 && r < 8) g_cfin[(isL0 ? 0 : HID) + m0 + r] = creg;
}

// ---------------- output projection + final states --------------------------
__global__ void k_out(const float* __restrict__ W_out, const float* __restrict__ b_out,
                      float* __restrict__ out, int out_size) {
    int wid = threadIdx.x >> 5, lane = threadIdx.x & 31;
    int t = blockIdx.x * 8 + wid;
    float acc = 0.f;
    #pragma unroll
    for (int j = 0; j < 16; ++j) {
        int k = j * 32 + lane;
        acc += __uint_as_float((unsigned)g_th2[(size_t)t * HID + k]) * W_out[k];
    }
    #pragma unroll
    for (int o = 16; o; o >>= 1) acc += __shfl_down_sync(0xffffffffu, acc, o);
    if (lane == 0 && t < out_size) out[t] = acc + b_out[0];

    if (blockIdx.x == 0 && out_size >= TT + 2048) {
        for (int i = threadIdx.x; i < 512; i += 256) {
            out[TT + i]        = __uint_as_float((unsigned)g_th1[(size_t)(TT - 1) * HID + i]);
            out[TT + 512 + i]  = __uint_as_float((unsigned)g_th2[(size_t)(TT - 1) * HID + i]);
            out[TT + 1024 + i] = g_cfin[i];
            out[TT + 1536 + i] = g_cfin[512 + i];
        }
    }
}

// ---------------- launch -----------------------------------------------------
extern "C" void kernel_launch(void* const* d_in, const int* in_sizes, int n_in,
                              void* d_out, int out_size) {
    const float* in_states = (const float*)d_in[0];
    const float* W_in  = (const float*)d_in[1];
    const float* b_in  = (const float*)d_in[2];
    const float* W_ih0 = (const float*)d_in[3];
    const float* W_hh0 = (const float*)d_in[4];
    const float* b_ih0 = (const float*)d_in[5];
    const float* b_hh0 = (const float*)d_in[6];
    const float* W_ih1 = (const float*)d_in[7];
    const float* W_hh1 = (const float*)d_in[8];
    const float* b_ih1 = (const float*)d_in[9];
    const float* b_hh1 = (const float*)d_in[10];
    const float* W_out = (const float*)d_in[11];
    const float* b_out = (const float*)d_in[12];

    k_clear<<<2048, 1024>>>();   // (TT*HID/2) ulonglong2 per array
    k_fold<<<2048, 64>>>(W_ih0, W_in, b_in, b_ih0, b_hh0);
    k_xg0<<<dim3(2048 / 256, TT / 16), 256>>>(in_states);
    k_rec<<<G0 + G1, 512>>>(W_hh0, W_ih1, W_hh1, b_ih1, b_hh1);
    k_out<<<TT / 8, 256>>>(W_out, b_out, (float*)d_out, out_size);
}

// round 4
// speedup vs baseline: 2.0693x; 1.0116x over previous
#include <cuda_runtime.h>
#include <cstdint>

#define TT   8192
#define HID  512
#define EE   256
#define ING  40
#define G0   64
#define G1   64

typedef unsigned long long ULL;

// ---------------- device scratch (static globals: no allocation) ------------
__device__ float g_xg0[TT * 2048];    // 64 MB: precomputed input gates, layer 0
__device__ ULL   g_th1[TT * HID];     // 32 MB: tagged h1 history {tag<<32 | f32}
__device__ ULL   g_th2[TT * HID];     // 32 MB: tagged h2 history
__device__ float g_weff[2048 * ING];  // folded W_ih0 @ W_in
__device__ float g_beff[2048];        // folded bias
__device__ float g_cfin[2 * HID];     // final cell states

// ---------------- PTX helpers ------------------------------------------------
__device__ __forceinline__ ULL ld_rlx(const ULL* p) {
    ULL v;
    asm volatile("ld.relaxed.gpu.global.b64 %0, [%1];" : "=l"(v) : "l"(p) : "memory");
    return v;
}
__device__ __forceinline__ void st_rlx(ULL* p, ULL v) {
    asm volatile("st.relaxed.gpu.global.b64 [%0], %1;" :: "l"(p), "l"(v) : "memory");
}
__device__ __forceinline__ ULL fma2(ULL a, ULL b, ULL c) {
    ULL d;
    asm("fma.rn.f32x2 %0, %1, %2, %3;" : "=l"(d) : "l"(a), "l"(b), "l"(c));
    return d;
}
__device__ __forceinline__ ULL add2(ULL a, ULL b) {
    ULL d;
    asm("add.rn.f32x2 %0, %1, %2;" : "=l"(d) : "l"(a), "l"(b));
    return d;
}
__device__ __forceinline__ void unpack2(ULL v, float& lo, float& hi) {
    asm("mov.b64 {%0, %1}, %2;" : "=f"(lo), "=f"(hi) : "l"(v));
}
// single-MUFU activations (sm_75+): tanh.approx + sigmoid via tanh
__device__ __forceinline__ float tanh_apx(float x) {
    float y; asm("tanh.approx.f32 %0, %1;" : "=f"(y) : "f"(x)); return y;
}
__device__ __forceinline__ float sig_apx(float x) {
    return fmaf(0.5f, tanh_apx(0.5f * x), 0.5f);
}

// ---------------- clear tag arrays (must run every launch / replay) ---------
__global__ void k_clear() {
    size_t i = (size_t)blockIdx.x * blockDim.x + threadIdx.x;   // 2,097,152 threads
    ulonglong2 z = make_ulonglong2(0ull, 0ull);
    ((ulonglong2*)g_th1)[i] = z;
    ((ulonglong2*)g_th2)[i] = z;
}

// ---------------- fold input projection into layer-0 input weights ----------
__global__ void k_fold(const float* __restrict__ W_ih0, const float* __restrict__ W_in,
                       const float* __restrict__ b_in,  const float* __restrict__ b_ih0,
                       const float* __restrict__ b_hh0) {
    __shared__ float srow[EE];
    int j = blockIdx.x;
    for (int e = threadIdx.x; e < EE; e += 64) srow[e] = W_ih0[(size_t)j * EE + e];
    __syncthreads();
    if (threadIdx.x < ING) {
        int i = threadIdx.x;
        float s = 0.f;
        #pragma unroll 8
        for (int e = 0; e < EE; ++e) s += srow[e] * W_in[e * ING + i];
        g_weff[(size_t)j * ING + i] = s;
    } else if (threadIdx.x == ING) {
        float s = 0.f;
        #pragma unroll 8
        for (int e = 0; e < EE; ++e) s += srow[e] * b_in[e];
        g_beff[j] = s + b_ih0[j] + b_hh0[j];
    }
}

// ---------------- precompute xg0[t][j] = in_states[t] @ Weff[j] + beff[j] ---
__global__ void k_xg0(const float* __restrict__ in_states) {
    __shared__ float s_in[16 * ING];
    const int t0 = blockIdx.y * 16;
    const int j  = blockIdx.x * 256 + threadIdx.x;
    for (int idx = threadIdx.x; idx < 16 * ING; idx += 256)
        s_in[idx] = in_states[(size_t)t0 * ING + idx];
    __syncthreads();

    float wreg[ING];
    const float4* wp = (const float4*)(g_weff + (size_t)j * ING);
    #pragma unroll
    for (int u = 0; u < ING / 4; ++u) ((float4*)wreg)[u] = wp[u];

    float acc[16];
    float b = g_beff[j];
    #pragma unroll
    for (int tt = 0; tt < 16; ++tt) acc[tt] = b;
    #pragma unroll
    for (int i = 0; i < ING; ++i) {
        float wv = wreg[i];
        #pragma unroll
        for (int tt = 0; tt < 16; ++tt) acc[tt] += wv * s_in[tt * ING + i];
    }
    #pragma unroll
    for (int tt = 0; tt < 16; ++tt)
        g_xg0[(size_t)(t0 + tt) * 2048 + j] = acc[tt];
}

// ---------------- persistent recurrent kernel: both LSTM layers -------------
// blocks 0..63: layer 0;  blocks 64..127: layer 1.
// Readiness = tag embedded in the 64-bit h word (single L2 hop).
// L1 pre-phase: h1[t] is always ahead (L0 free-runs) -> poll+stage+W_ih1 FMAs
// BEFORE waiting on h2[t-1]; only the W_hh1 half sits on the critical chain.
__global__ void __launch_bounds__(512, 1) k_rec(
    const float* __restrict__ W_hh0, const float* __restrict__ W_ih1,
    const float* __restrict__ W_hh1, const float* __restrict__ b_ih1,
    const float* __restrict__ b_hh1) {
    __shared__ __align__(16) float sh1[HID];        // L1: h1[t] slices
    __shared__ __align__(16) float sh2[HID];        // recurrent h(t-1) slices
    __shared__ __align__(16) float part[2][512];

    const int  tid  = threadIdx.x;
    const int  w    = tid >> 5;
    const int  r    = tid & 31;
    const bool isL0 = (blockIdx.x < G0);
    const int  cl   = isL0 ? blockIdx.x : (blockIdx.x - G0);
    const int  m0   = cl * 8;
    const int  q    = r >> 3, ml = r & 7;
    const int  grow = q * 512 + m0 + ml;            // global gate row

    // weights in registers, packed f32x2
    ULL wa[16];
    {
        const ULL* pa = (const ULL*)((isL0 ? W_hh0 : W_hh1) + (size_t)grow * HID + w * 32);
        #pragma unroll
        for (int u = 0; u < 16; ++u) wa[u] = pa[u];
    }
    ULL wb[16];
    if (!isL0) {
        const ULL* pb = (const ULL*)(W_ih1 + (size_t)grow * HID + w * 32);
        #pragma unroll
        for (int u = 0; u < 16; ++u) wb[u] = pb[u];
    }
    const float bias_c = isL0 ? 0.f : (b_ih1[grow] + b_hh1[grow]);

    ULL* trec = isL0 ? g_th1 : g_th2;    // own recurrent stream (read t-1, write t)

    // rolling poll/publish pointers (avoid per-step IMADs on the chain)
    const ULL* pA   = g_th1 + (size_t)w * 32 + r;                 // h1[t], L1 only
    const ULL* pB   = trec - HID + (size_t)w * 32 + r;            // h(t-1)
    ULL*       pPub = trec + (size_t)m0 + r;                      // warp0 lanes r<8

    float creg = 0.f;
    float xg_next = 0.f, xg_next2 = 0.f;
    if (isL0 && w == 0) {
        xg_next  = __ldcg(&g_xg0[grow]);                      // t = 0
        xg_next2 = __ldcg(&g_xg0[2048 + grow]);               // t = 1
    }

    for (int t = 0; t < TT; ++t) {
        float xg_cur = xg_next;
        xg_next = xg_next2;
        if (isL0 && w == 0 && t + 2 < TT)
            xg_next2 = __ldcg(&g_xg0[(size_t)(t + 2) * 2048 + grow]);

        ULL a0 = 0, a1 = 0, a2 = 0, a3 = 0;

        // ---- pre-phase (L1 only): h1[t] is ahead; do the W_ih1 half now ----
        if (!isL0) {
            const unsigned wantA = (unsigned)(t + 1);
            ULL va = ld_rlx(pA);
            while ((unsigned)(va >> 32) != wantA) va = ld_rlx(pA);
            sh1[w * 32 + r] = __uint_as_float((unsigned)va);
            __syncwarp();
            const ULL* hp = (const ULL*)(sh1 + w * 32);
            #pragma unroll
            for (int u = 0; u < 4; ++u) {
                a0 = fma2(wb[4 * u + 0], hp[4 * u + 0], a0);
                a1 = fma2(wb[4 * u + 1], hp[4 * u + 1], a1);
                a2 = fma2(wb[4 * u + 2], hp[4 * u + 2], a2);
                a3 = fma2(wb[4 * u + 3], hp[4 * u + 3], a3);
            }
        }

        // ---- critical wait: recurrent h(t-1) ----
        if (t > 0) {
            const unsigned wantB = (unsigned)t;
            ULL vb = ld_rlx(pB);
            while ((unsigned)(vb >> 32) != wantB) vb = ld_rlx(pB);
            sh2[w * 32 + r] = __uint_as_float((unsigned)vb);
        } else {
            sh2[w * 32 + r] = 0.f;
        }
        __syncwarp();
        {
            const ULL* hq = (const ULL*)(sh2 + w * 32);
            #pragma unroll
            for (int u = 0; u < 4; ++u) {
                a0 = fma2(wa[4 * u + 0], hq[4 * u + 0], a0);
                a1 = fma2(wa[4 * u + 1], hq[4 * u + 1], a1);
                a2 = fma2(wa[4 * u + 2], hq[4 * u + 2], a2);
                a3 = fma2(wa[4 * u + 3], hq[4 * u + 3], a3);
            }
        }
        {
            ULL s = add2(add2(a0, a1), add2(a2, a3));
            float alo, ahi; unpack2(s, alo, ahi);
            part[t & 1][w * 32 + r] = alo + ahi;
        }
        __syncthreads();   // the only CTA-wide barrier per step

        // ---- warp 0: reduce, per-lane activation, shuffle, cell update ----
        if (w == 0) {
            const float* pbuf = part[t & 1];
            float v[16];
            #pragma unroll
            for (int u = 0; u < 16; ++u) v[u] = pbuf[u * 32 + r];
            float s0 = (v[0] + v[1]) + (v[2] + v[3]);
            float s1 = (v[4] + v[5]) + (v[6] + v[7]);
            float s2 = (v[8] + v[9]) + (v[10] + v[11]);
            float s3 = (v[12] + v[13]) + (v[14] + v[15]);
            float s  = ((s0 + s1) + (s2 + s3)) + (isL0 ? xg_cur : bias_c);

            // activation in ALL lanes first (q==2 -> tanh gate, else sigmoid)
            float act = (q == 2) ? tanh_apx(s) : sig_apx(s);
            float pi = __shfl_sync(0xffffffffu, act, ml);
            float pf = __shfl_sync(0xffffffffu, act, 8 + ml);
            float pg = __shfl_sync(0xffffffffu, act, 16 + ml);
            float po = __shfl_sync(0xffffffffu, act, 24 + ml);
            if (r < 8) {
                creg = pf * creg + pi * pg;
                float h = po * tanh_apx(creg);
                ULL word = ((ULL)(unsigned)(t + 1) << 32) | (ULL)__float_as_uint(h);
                st_rlx(pPub, word);
            }
        }
        pA += HID; pB += HID; pPub += HID;
    }

    if (w == 0 && r < 8) g_cfin[(isL0 ? 0 : HID) + m0 + r] = creg;
}

// ---------------- output projection + final states --------------------------
__global__ void k_out(const float* __restrict__ W_out, const float* __restrict__ b_out,
                      float* __restrict__ out, int out_size) {
    int wid = threadIdx.x >> 5, lane = threadIdx.x & 31;
    int t = blockIdx.x * 8 + wid;
    float acc = 0.f;
    #pragma unroll
    for (int j = 0; j < 16; ++j) {
        int k = j * 32 + lane;
        acc += __uint_as_float((unsigned)g_th2[(size_t)t * HID + k]) * W_out[k];
    }
    #pragma unroll
    for (int o = 16; o; o >>= 1) acc += __shfl_down_sync(0xffffffffu, acc, o);
    if (lane == 0 && t < out_size) out[t] = acc + b_out[0];

    if (blockIdx.x == 0 && out_size >= TT + 2048) {
        for (int i = threadIdx.x; i < 512; i += 256) {
            out[TT + i]        = __uint_as_float((unsigned)g_th1[(size_t)(TT - 1) * HID + i]);
            out[TT + 512 + i]  = __uint_as_float((unsigned)g_th2[(size_t)(TT - 1) * HID + i]);
            out[TT + 1024 + i] = g_cfin[i];
            out[TT + 1536 + i] = g_cfin[512 + i];
        }
    }
}

// ---------------- launch -----------------------------------------------------
extern "C" void kernel_launch(void* const* d_in, const int* in_sizes, int n_in,
                              void* d_out, int out_size) {
    const float* in_states = (const float*)d_in[0];
    const float* W_in  = (const float*)d_in[1];
    const float* b_in  = (const float*)d_in[2];
    const float* W_ih0 = (const float*)d_in[3];
    const float* W_hh0 = (const float*)d_in[4];
    const float* b_ih0 = (const float*)d_in[5];
    const float* b_hh0 = (const float*)d_in[6];
    const float* W_ih1 = (const float*)d_in[7];
    const float* W_hh1 = (const float*)d_in[8];
    const float* b_ih1 = (const float*)d_in[9];
    const float* b_hh1 = (const float*)d_in[10];
    const float* W_out = (const float*)d_in[11];
    const float* b_out = (const float*)d_in[12];

    k_clear<<<2048, 1024>>>();
    k_fold<<<2048, 64>>>(W_ih0, W_in, b_in, b_ih0, b_hh0);
    k_xg0<<<dim3(2048 / 256, TT / 16), 256>>>(in_states);
    k_rec<<<G0 + G1, 512>>>(W_hh0, W_ih1, W_hh1, b_ih1, b_hh1);
    k_out<<<TT / 8, 256>>>(W_out, b_out, (float*)d_out, out_size);
}